// round 12
// baseline (speedup 1.0000x reference)
#include <cuda_runtime.h>
#include <cuda_fp16.h>
#include <cstdint>

// Problem constants
#define BB 1024
#define UU 8
#define II 512
#define HH 512
#define GN 1536      // 3*H

// Fused GEMM tiling
#define TM 128                // batch rows per CTA
#define TOUT 64               // h-outputs per CTA
#define BROWS 192             // interleaved weight rows per CTA (TOUT/16 * 48)
#define KC 64                 // fp16 k per stage (128 B rows)
#define NPHASE 8              // k-steps per phase (512/64)
#define NSTEPS 16             // 2 phases
#define STAGES 4
#define ST_B (TM * 128)                       // A: 16 KB, then B: 24 KB
#define STAGE_BYTES (TM * 128 + BROWS * 128)  // 40 KB
#define SMEM_BYTES (STAGES * STAGE_BYTES)     // 160 KB

// ---------------------------------------------------------------------------
// Device scratch (fp16 converted inputs)
// ---------------------------------------------------------------------------
__device__ __half g_xh [(size_t)UU * BB * II];   // [U][B][K]
__device__ __half g_hh [(size_t)UU * BB * II];   // [U][B][K]
// gate-interleaved weights: row c = (j/16)*48 + gate*16 + (j%16), per unit
__device__ __half g_wih[(size_t)UU * GN * II];
__device__ __half g_whh[(size_t)UU * GN * II];

// ---------------------------------------------------------------------------
// helpers
// ---------------------------------------------------------------------------
__device__ __forceinline__ uint32_t smem_u32(const void* p) {
    return (uint32_t)__cvta_generic_to_shared(p);
}
__device__ __forceinline__ uint32_t sw128(uint32_t off) {
    return off ^ ((off >> 3) & 0x70);
}

#define CP_ASYNC16(dst, src) \
    asm volatile("cp.async.cg.shared.global [%0], [%1], 16;" :: "r"(dst), "l"(src))
#define CP_COMMIT() asm volatile("cp.async.commit_group;" ::: "memory")
#define CP_WAIT2()  asm volatile("cp.async.wait_group 2;" ::: "memory")

#define LDMATRIX_X4(r0, r1, r2, r3, addr) \
    asm volatile("ldmatrix.sync.aligned.m8n8.x4.shared.b16 {%0,%1,%2,%3}, [%4];" \
                 : "=r"(r0), "=r"(r1), "=r"(r2), "=r"(r3) : "r"(addr))

#define MMA_16816_F16(c, a, b0, b1) \
    asm volatile("mma.sync.aligned.m16n8k16.row.col.f32.f16.f16.f32 " \
                 "{%0,%1,%2,%3}, {%4,%5,%6,%7}, {%8,%9}, {%0,%1,%2,%3};" \
                 : "+f"((c)[0]), "+f"((c)[1]), "+f"((c)[2]), "+f"((c)[3]) \
                 : "r"((a)[0]), "r"((a)[1]), "r"((a)[2]), "r"((a)[3]), \
                   "r"(b0), "r"(b1))

// ---------------------------------------------------------------------------
// Combined fp32 -> fp16 conversion for all four tensors, 4 elems/thread.
//  segment 0: inputs  -> g_xh, de-interleave [B][U] -> [U][B]
//  segment 1: hidden  -> g_hh, de-interleave
//  segment 2: W_ih    -> g_wih, gate-interleave rows
//  segment 3: W_hh    -> g_whh, gate-interleave rows
// ---------------------------------------------------------------------------
#define ACT4  (BB * UU * II / 4)     // 1,048,576 per activation tensor
#define WW4   (UU * GN * II / 4)     // 1,572,864 per weight tensor
#define TOT4  (2 * ACT4 + 2 * WW4)   // 5,242,880

__global__ __launch_bounds__(256) void cvt_all_kernel(
    const float4* __restrict__ X,  const float4* __restrict__ Hi,
    const float4* __restrict__ Wi, const float4* __restrict__ Wh)
{
    const int i = blockIdx.x * blockDim.x + threadIdx.x;
    if (i >= TOT4) return;

    const float4* src;
    __half* dst;
    int ii;
    bool act;
    if (i < 2 * ACT4) {
        act = true;
        if (i < ACT4) { src = X;  dst = g_xh; ii = i; }
        else          { src = Hi; dst = g_hh; ii = i - ACT4; }
    } else {
        act = false;
        const int iw = i - 2 * ACT4;
        if (iw < WW4) { src = Wi; dst = g_wih; ii = iw; }
        else          { src = Wh; dst = g_whh; ii = iw - WW4; }
    }

    const int k4  = ii & 127;         // 512/4 = 128 float4 per row
    const int row = ii >> 7;

    const float4 v = src[ii];
    __half2 p01 = __floats2half2_rn(v.x, v.y);
    __half2 p23 = __floats2half2_rn(v.z, v.w);
    uint2 pack;
    pack.x = *reinterpret_cast<uint32_t*>(&p01);
    pack.y = *reinterpret_cast<uint32_t*>(&p23);

    int drow;
    if (act) {
        // [B][U] -> [U][B]
        drow = (row & 7) * BB + (row >> 3);
    } else {
        // row = u*1536 + g*512 + j  ->  u*1536 + (j/16)*48 + g*16 + (j%16)
        const int u    = row / GN;
        const int grow = row - u * GN;
        const int g    = grow >> 9;
        const int j    = grow & 511;
        drow = u * GN + (j >> 4) * 48 + g * 16 + (j & 15);
    }
    reinterpret_cast<uint2*>(dst + (size_t)drow * II)[k4] = pack;
}

// ---------------------------------------------------------------------------
// Fused dual-GEMM + GRU gates.
//  phase 0: acc_rz += X*Wih(r,z); acc_xn = X*Wih(n)
//  phase 1: acc_rz += H*Whh(r,z); acc_hn = H*Whh(n)
//  epilogue: r=sig(acc_r+br), z=sig(acc_z+bz), n=tanh(xn+bni + r*(hn+bnh)),
//            out = (1-z)*n + z*h
// CTA: 128 batch rows x 64 outputs; 8 warps (2M x 4jb), warp 64 rows x 16 out.
// grid = (8 jblk, 8 mblk, 8 u) = 512 CTAs.
// ---------------------------------------------------------------------------
__global__ __launch_bounds__(256, 1) void gru_fused_kernel(
    const float* __restrict__ Hi,     // hidden [B][U][H] fp32
    const float* __restrict__ bih,
    const float* __restrict__ bhh,
    float* __restrict__ out)
{
    extern __shared__ __align__(1024) char smem[];

    const int jblk = blockIdx.x;          // 64 outputs
    const int m0   = blockIdx.y * TM;
    const int u    = blockIdx.z;

    const int tid  = threadIdx.x;
    const int wid  = tid >> 5;
    const int lane = tid & 31;
    const int wm   = wid & 1;             // M half (0..1)
    const int wjb  = wid >> 1;            // output sub-block (0..3)

    const uint32_t sb = smem_u32(smem);

    const __half* __restrict__ aX  = g_xh  + ((size_t)u * BB + m0) * II;
    const __half* __restrict__ aH  = g_hh  + ((size_t)u * BB + m0) * II;
    const __half* __restrict__ bW0 = g_wih + ((size_t)u * GN + jblk * BROWS) * II;
    const __half* __restrict__ bW1 = g_whh + ((size_t)u * GN + jblk * BROWS) * II;

    // per-thread loader base (same shape for A and B; chunk j adds 32 rows)
    const uint32_t l_soff = sw128((uint32_t)((tid >> 3) * 128 + (tid & 7) * 16));
    const uint32_t l_goff = (uint32_t)((tid >> 3) * II + (tid & 7) * 8);

    // ---------- fragment address precompute (proven R11 k-major b16) ----------
    const uint32_t a_row  = (uint32_t)(lane & 15);
    const uint32_t a_colB = (uint32_t)((lane >> 4) << 4);
    uint32_t a_frag_off[4];
    #pragma unroll
    for (int mt = 0; mt < 4; ++mt)
        a_frag_off[mt] = (uint32_t)((wm * 64 + mt * 16 + a_row) * 128) + a_colB;

    const uint32_t b_row  = (uint32_t)((lane & 7) | ((lane >> 4) << 3));
    const uint32_t b_colB = (uint32_t)(((lane >> 3) & 1) << 4);
    uint32_t b_frag_off[3];
    #pragma unroll
    for (int g3 = 0; g3 < 3; ++g3)
        b_frag_off[g3] = (uint32_t)((wjb * 48 + g3 * 16 + b_row) * 128) + b_colB;

    // accumulators: r,z shared across phases; xn / hn separate
    float acc_rz[4][4][4];   // [mt][r0,r1,z0,z1][quad]
    float acc_xn[4][2][4];
    float acc_hn[4][2][4];
    #pragma unroll
    for (int mt = 0; mt < 4; ++mt) {
        #pragma unroll
        for (int c = 0; c < 4; ++c)
            #pragma unroll
            for (int q = 0; q < 4; ++q) acc_rz[mt][c][q] = 0.0f;
        #pragma unroll
        for (int c = 0; c < 2; ++c)
            #pragma unroll
            for (int q = 0; q < 4; ++q) { acc_xn[mt][c][q] = 0.0f; acc_hn[mt][c][q] = 0.0f; }
    }

    // ---------- stage load (phase selected by step index) ----------
    auto load_stage = [&](int s) {
        const uint32_t base = sb + (uint32_t)(s & (STAGES - 1)) * STAGE_BYTES;
        const __half* __restrict__ Ab = (s < NPHASE) ? aX  : aH;
        const __half* __restrict__ Bb = (s < NPHASE) ? bW0 : bW1;
        const uint32_t koff = (uint32_t)(s & (NPHASE - 1)) * KC;
        #pragma unroll
        for (int j = 0; j < 4; ++j)            // A: 128 rows
            CP_ASYNC16(base + l_soff + j * 4096, Ab + l_goff + (size_t)j * 32 * II + koff);
        #pragma unroll
        for (int j = 0; j < 6; ++j)            // B: 192 rows
            CP_ASYNC16(base + ST_B + l_soff + j * 4096, Bb + l_goff + (size_t)j * 32 * II + koff);
    };

    // prologue: stages 0..2
    #pragma unroll
    for (int p = 0; p < STAGES - 1; ++p) { load_stage(p); CP_COMMIT(); }

    for (int s = 0; s < NSTEPS; ++s) {
        CP_WAIT2();
        __syncthreads();

        if (s + STAGES - 1 < NSTEPS) load_stage(s + STAGES - 1);
        CP_COMMIT();

        const uint32_t As = sb + (uint32_t)(s & (STAGES - 1)) * STAGE_BYTES;
        const uint32_t Bs = As + ST_B;
        const bool ph0 = (s < NPHASE);

        #pragma unroll
        for (int kk = 0; kk < 4; ++kk) {        // 4 x k16 within KC=64
            uint32_t a[4][4], b[3][4];
            #pragma unroll
            for (int mt = 0; mt < 4; ++mt) {
                const uint32_t addr = As + sw128(a_frag_off[mt] + kk * 32);
                LDMATRIX_X4(a[mt][0], a[mt][1], a[mt][2], a[mt][3], addr);
            }
            #pragma unroll
            for (int g3 = 0; g3 < 3; ++g3) {
                const uint32_t addr = Bs + sw128(b_frag_off[g3] + kk * 32);
                LDMATRIX_X4(b[g3][0], b[g3][1], b[g3][2], b[g3][3], addr);
            }
            #pragma unroll
            for (int mt = 0; mt < 4; ++mt) {
                // r, z gates -> shared accumulators
                MMA_16816_F16(acc_rz[mt][0], a[mt], b[0][0], b[0][1]);
                MMA_16816_F16(acc_rz[mt][1], a[mt], b[0][2], b[0][3]);
                MMA_16816_F16(acc_rz[mt][2], a[mt], b[1][0], b[1][1]);
                MMA_16816_F16(acc_rz[mt][3], a[mt], b[1][2], b[1][3]);
                // n gate -> phase-specific accumulators
                if (ph0) {
                    MMA_16816_F16(acc_xn[mt][0], a[mt], b[2][0], b[2][1]);
                    MMA_16816_F16(acc_xn[mt][1], a[mt], b[2][2], b[2][3]);
                } else {
                    MMA_16816_F16(acc_hn[mt][0], a[mt], b[2][0], b[2][1]);
                    MMA_16816_F16(acc_hn[mt][1], a[mt], b[2][2], b[2][3]);
                }
            }
        }
    }

    // ---------- epilogue: gate math, write out directly ----------
    const int gr = lane >> 2;        // 0..7 row within 8-row group
    const int d  = lane & 3;         // 0..3 col pair
    const int j0 = jblk * TOUT + wjb * 16;

    // biases (loop-invariant over mt): per nb, per col c
    float brs[2][2], bzs[2][2], bni[2][2], bnh[2][2];
    #pragma unroll
    for (int nb = 0; nb < 2; ++nb) {
        #pragma unroll
        for (int c = 0; c < 2; ++c) {
            const int j = j0 + nb * 8 + 2 * d + c;
            brs[nb][c] = __ldg(bih + u * GN + j)        + __ldg(bhh + u * GN + j);
            bzs[nb][c] = __ldg(bih + u * GN + 512 + j)  + __ldg(bhh + u * GN + 512 + j);
            bni[nb][c] = __ldg(bih + u * GN + 1024 + j);
            bnh[nb][c] = __ldg(bhh + u * GN + 1024 + j);
        }
    }

    #pragma unroll
    for (int mt = 0; mt < 4; ++mt) {
        const int r0 = m0 + wm * 64 + mt * 16 + gr;
        #pragma unroll
        for (int rh = 0; rh < 2; ++rh) {
            const int row = r0 + rh * 8;
            const float* __restrict__ hp = Hi + ((size_t)row * UU + u) * HH;
            float* __restrict__ op = out + ((size_t)row * UU + u) * HH;
            #pragma unroll
            for (int nb = 0; nb < 2; ++nb) {
                const int jc = j0 + nb * 8 + 2 * d;
                const float2 h2 = *reinterpret_cast<const float2*>(hp + jc);
                float2 o2;
                #pragma unroll
                for (int c = 0; c < 2; ++c) {
                    const int q = rh * 2 + c;
                    const float rr = 1.0f / (1.0f + __expf(-(acc_rz[mt][nb][q]     + brs[nb][c])));
                    const float zz = 1.0f / (1.0f + __expf(-(acc_rz[mt][nb + 2][q] + bzs[nb][c])));
                    const float nn = tanhf(acc_xn[mt][nb][q] + bni[nb][c] +
                                           rr * (acc_hn[mt][nb][q] + bnh[nb][c]));
                    const float hv = c ? h2.y : h2.x;
                    const float ov = (1.0f - zz) * nn + zz * hv;
                    if (c) o2.y = ov; else o2.x = ov;
                }
                *reinterpret_cast<float2*>(op + jc) = o2;
            }
        }
    }
}

// ---------------------------------------------------------------------------
extern "C" void kernel_launch(void* const* d_in, const int* in_sizes, int n_in,
                              void* d_out, int out_size)
{
    const float* inputs = (const float*)d_in[0];  // [B,U,I]
    const float* hidden = (const float*)d_in[1];  // [B,U,H]
    const float* W_ih   = (const float*)d_in[2];  // [U,3H,I]
    const float* W_hh   = (const float*)d_in[3];  // [U,3H,H]
    const float* b_ih   = (const float*)d_in[4];  // [U,3H]
    const float* b_hh   = (const float*)d_in[5];  // [U,3H]
    float* out = (float*)d_out;                   // [B,U,H]

    cudaFuncSetAttribute(gru_fused_kernel,
                         cudaFuncAttributeMaxDynamicSharedMemorySize, SMEM_BYTES);

    cvt_all_kernel<<<(TOT4 + 255) / 256, 256>>>(
        (const float4*)inputs, (const float4*)hidden,
        (const float4*)W_ih,   (const float4*)W_hh);

    dim3 grid(HH / TOUT, BB / TM, UU);            // (8, 8, 8) = 512 CTAs
    gru_fused_kernel<<<grid, 256, SMEM_BYTES>>>(hidden, b_ih, b_hh, out);
}

// round 13
// speedup vs baseline: 1.3435x; 1.3435x over previous
#include <cuda_runtime.h>
#include <cuda_fp16.h>
#include <cstdint>

// Problem constants
#define BB 1024
#define UU 8
#define II 512
#define HH 512
#define GN 1536      // 3*H

// Fused GEMM tiling (small CTA for 2 CTAs/SM)
#define TM 128                // batch rows per CTA
#define TOUT 32               // h-outputs per CTA
#define BROWS 96              // interleaved weight rows (TOUT/16 * 48)
#define KC 64                 // fp16 k per stage (128 B rows)
#define NPHASE 8              // k-steps per phase (512/64)
#define NSTEPS 16             // 2 phases
#define STAGES 3
#define ST_B (TM * 128)                       // A: 16 KB, then B: 12 KB
#define STAGE_BYTES (TM * 128 + BROWS * 128)  // 28 KB
#define SMEM_BYTES (STAGES * STAGE_BYTES)     // 84 KB

// ---------------------------------------------------------------------------
// Device scratch (fp16 converted inputs)
// ---------------------------------------------------------------------------
__device__ __half g_xh [(size_t)UU * BB * II];   // [U][B][K]
__device__ __half g_hh [(size_t)UU * BB * II];   // [U][B][K]
// gate-interleaved weights: row c = (j/16)*48 + gate*16 + (j%16), per unit
__device__ __half g_wih[(size_t)UU * GN * II];
__device__ __half g_whh[(size_t)UU * GN * II];

// ---------------------------------------------------------------------------
// helpers
// ---------------------------------------------------------------------------
__device__ __forceinline__ uint32_t smem_u32(const void* p) {
    return (uint32_t)__cvta_generic_to_shared(p);
}
__device__ __forceinline__ uint32_t sw128(uint32_t off) {
    return off ^ ((off >> 3) & 0x70);
}

#define CP_ASYNC16(dst, src) \
    asm volatile("cp.async.cg.shared.global [%0], [%1], 16;" :: "r"(dst), "l"(src))
#define CP_COMMIT() asm volatile("cp.async.commit_group;" ::: "memory")
#define CP_WAIT1()  asm volatile("cp.async.wait_group 1;" ::: "memory")

#define LDMATRIX_X4(r0, r1, r2, r3, addr) \
    asm volatile("ldmatrix.sync.aligned.m8n8.x4.shared.b16 {%0,%1,%2,%3}, [%4];" \
                 : "=r"(r0), "=r"(r1), "=r"(r2), "=r"(r3) : "r"(addr))

#define MMA_16816_F16(c, a, b0, b1) \
    asm volatile("mma.sync.aligned.m16n8k16.row.col.f32.f16.f16.f32 " \
                 "{%0,%1,%2,%3}, {%4,%5,%6,%7}, {%8,%9}, {%0,%1,%2,%3};" \
                 : "+f"((c)[0]), "+f"((c)[1]), "+f"((c)[2]), "+f"((c)[3]) \
                 : "r"((a)[0]), "r"((a)[1]), "r"((a)[2]), "r"((a)[3]), \
                   "r"(b0), "r"(b1))

// ---------------------------------------------------------------------------
// Combined fp32 -> fp16 conversion for all four tensors, 4 elems/thread.
// ---------------------------------------------------------------------------
#define ACT4  (BB * UU * II / 4)     // 1,048,576 per activation tensor
#define WW4   (UU * GN * II / 4)     // 1,572,864 per weight tensor
#define TOT4  (2 * ACT4 + 2 * WW4)   // 5,242,880

__global__ __launch_bounds__(256) void cvt_all_kernel(
    const float4* __restrict__ X,  const float4* __restrict__ Hi,
    const float4* __restrict__ Wi, const float4* __restrict__ Wh)
{
    const int i = blockIdx.x * blockDim.x + threadIdx.x;
    if (i >= TOT4) return;

    const float4* src;
    __half* dst;
    int ii;
    bool act;
    if (i < 2 * ACT4) {
        act = true;
        if (i < ACT4) { src = X;  dst = g_xh; ii = i; }
        else          { src = Hi; dst = g_hh; ii = i - ACT4; }
    } else {
        act = false;
        const int iw = i - 2 * ACT4;
        if (iw < WW4) { src = Wi; dst = g_wih; ii = iw; }
        else          { src = Wh; dst = g_whh; ii = iw - WW4; }
    }

    const int k4  = ii & 127;         // 512/4 = 128 float4 per row
    const int row = ii >> 7;

    const float4 v = src[ii];
    __half2 p01 = __floats2half2_rn(v.x, v.y);
    __half2 p23 = __floats2half2_rn(v.z, v.w);
    uint2 pack;
    pack.x = *reinterpret_cast<uint32_t*>(&p01);
    pack.y = *reinterpret_cast<uint32_t*>(&p23);

    int drow;
    if (act) {
        drow = (row & 7) * BB + (row >> 3);                    // [B][U] -> [U][B]
    } else {
        const int u    = row / GN;
        const int grow = row - u * GN;
        const int g    = grow >> 9;
        const int j    = grow & 511;
        drow = u * GN + (j >> 4) * 48 + g * 16 + (j & 15);     // gate-interleave
    }
    reinterpret_cast<uint2*>(dst + (size_t)drow * II)[k4] = pack;
}

// ---------------------------------------------------------------------------
// Fused dual-GEMM + GRU gates (2 CTAs/SM).
// CTA: 128 batch rows x 32 outputs; 8 warps (4M x 2jb), warp 32 rows x 16 out.
// grid = (16 jblk, 8 mblk, 8 u) = 1024 CTAs.
// ---------------------------------------------------------------------------
__global__ __launch_bounds__(256, 2) void gru_fused_kernel(
    const float* __restrict__ Hi,     // hidden [B][U][H] fp32
    const float* __restrict__ bih,
    const float* __restrict__ bhh,
    float* __restrict__ out)
{
    extern __shared__ __align__(1024) char smem[];

    const int jblk = blockIdx.x;          // 32 outputs
    const int m0   = blockIdx.y * TM;
    const int u    = blockIdx.z;

    const int tid  = threadIdx.x;
    const int wid  = tid >> 5;
    const int lane = tid & 31;
    const int wm   = wid & 3;             // M quarter (0..3)
    const int wjb  = wid >> 2;            // output sub-block (0..1)

    const uint32_t sb = smem_u32(smem);

    const __half* __restrict__ aX  = g_xh  + ((size_t)u * BB + m0) * II;
    const __half* __restrict__ aH  = g_hh  + ((size_t)u * BB + m0) * II;
    const __half* __restrict__ bW0 = g_wih + ((size_t)u * GN + jblk * BROWS) * II;
    const __half* __restrict__ bW1 = g_whh + ((size_t)u * GN + jblk * BROWS) * II;

    // per-thread loader base
    const uint32_t l_soff = sw128((uint32_t)((tid >> 3) * 128 + (tid & 7) * 16));
    const uint32_t l_goff = (uint32_t)((tid >> 3) * II + (tid & 7) * 8);

    // ---------- fragment address precompute ----------
    const uint32_t a_row  = (uint32_t)(lane & 15);
    const uint32_t a_colB = (uint32_t)((lane >> 4) << 4);
    uint32_t a_frag_off[2];
    #pragma unroll
    for (int mt = 0; mt < 2; ++mt)
        a_frag_off[mt] = (uint32_t)((wm * 32 + mt * 16 + a_row) * 128) + a_colB;

    const uint32_t b_row  = (uint32_t)((lane & 7) | ((lane >> 4) << 3));
    const uint32_t b_colB = (uint32_t)(((lane >> 3) & 1) << 4);
    uint32_t b_frag_off[3];
    #pragma unroll
    for (int g3 = 0; g3 < 3; ++g3)
        b_frag_off[g3] = (uint32_t)((wjb * 48 + g3 * 16 + b_row) * 128) + b_colB;

    // accumulators: r,z shared across phases; xn / hn separate
    float acc_rz[2][4][4];   // [mt][r0,r1,z0,z1][quad]
    float acc_xn[2][2][4];
    float acc_hn[2][2][4];
    #pragma unroll
    for (int mt = 0; mt < 2; ++mt) {
        #pragma unroll
        for (int c = 0; c < 4; ++c)
            #pragma unroll
            for (int q = 0; q < 4; ++q) acc_rz[mt][c][q] = 0.0f;
        #pragma unroll
        for (int c = 0; c < 2; ++c)
            #pragma unroll
            for (int q = 0; q < 4; ++q) { acc_xn[mt][c][q] = 0.0f; acc_hn[mt][c][q] = 0.0f; }
    }

    // ---------- stage load: k-step s into smem stage st ----------
    auto load_stage = [&](int s, int st) {
        const uint32_t base = sb + (uint32_t)st * STAGE_BYTES;
        const __half* __restrict__ Ab = (s < NPHASE) ? aX  : aH;
        const __half* __restrict__ Bb = (s < NPHASE) ? bW0 : bW1;
        const uint32_t koff = (uint32_t)(s & (NPHASE - 1)) * KC;
        #pragma unroll
        for (int j = 0; j < 4; ++j)            // A: 128 rows
            CP_ASYNC16(base + l_soff + j * 4096, Ab + l_goff + (size_t)j * 32 * II + koff);
        #pragma unroll
        for (int j = 0; j < 3; ++j)            // B: 96 rows
            CP_ASYNC16(base + ST_B + l_soff + j * 4096, Bb + l_goff + (size_t)j * 32 * II + koff);
    };

    // prologue: stages 0,1
    load_stage(0, 0); CP_COMMIT();
    load_stage(1, 1); CP_COMMIT();

    int rd_st = 0, ld_st = 2;
    for (int s = 0; s < NSTEPS; ++s) {
        CP_WAIT1();              // stage s complete (only s+1 may be pending)
        __syncthreads();         // visibility; all warps done with stage s-1

        if (s + 2 < NSTEPS) load_stage(s + 2, ld_st);
        CP_COMMIT();
        if (++ld_st == STAGES) ld_st = 0;

        const uint32_t As = sb + (uint32_t)rd_st * STAGE_BYTES;
        const uint32_t Bs = As + ST_B;
        if (++rd_st == STAGES) rd_st = 0;
        const bool ph0 = (s < NPHASE);

        #pragma unroll
        for (int kk = 0; kk < 4; ++kk) {        // 4 x k16 within KC=64
            uint32_t a[2][4], b[3][4];
            #pragma unroll
            for (int mt = 0; mt < 2; ++mt) {
                const uint32_t addr = As + sw128(a_frag_off[mt] + kk * 32);
                LDMATRIX_X4(a[mt][0], a[mt][1], a[mt][2], a[mt][3], addr);
            }
            #pragma unroll
            for (int g3 = 0; g3 < 3; ++g3) {
                const uint32_t addr = Bs + sw128(b_frag_off[g3] + kk * 32);
                LDMATRIX_X4(b[g3][0], b[g3][1], b[g3][2], b[g3][3], addr);
            }
            #pragma unroll
            for (int mt = 0; mt < 2; ++mt) {
                MMA_16816_F16(acc_rz[mt][0], a[mt], b[0][0], b[0][1]);
                MMA_16816_F16(acc_rz[mt][1], a[mt], b[0][2], b[0][3]);
                MMA_16816_F16(acc_rz[mt][2], a[mt], b[1][0], b[1][1]);
                MMA_16816_F16(acc_rz[mt][3], a[mt], b[1][2], b[1][3]);
                if (ph0) {
                    MMA_16816_F16(acc_xn[mt][0], a[mt], b[2][0], b[2][1]);
                    MMA_16816_F16(acc_xn[mt][1], a[mt], b[2][2], b[2][3]);
                } else {
                    MMA_16816_F16(acc_hn[mt][0], a[mt], b[2][0], b[2][1]);
                    MMA_16816_F16(acc_hn[mt][1], a[mt], b[2][2], b[2][3]);
                }
            }
        }
    }

    // ---------- epilogue: gate math, write out directly ----------
    const int gr = lane >> 2;        // 0..7 row within 8-row group
    const int d  = lane & 3;         // 0..3 col pair
    const int j0 = jblk * TOUT + wjb * 16;

    float brs[2][2], bzs[2][2], bni[2][2], bnh[2][2];
    #pragma unroll
    for (int nb = 0; nb < 2; ++nb) {
        #pragma unroll
        for (int c = 0; c < 2; ++c) {
            const int j = j0 + nb * 8 + 2 * d + c;
            brs[nb][c] = __ldg(bih + u * GN + j)        + __ldg(bhh + u * GN + j);
            bzs[nb][c] = __ldg(bih + u * GN + 512 + j)  + __ldg(bhh + u * GN + 512 + j);
            bni[nb][c] = __ldg(bih + u * GN + 1024 + j);
            bnh[nb][c] = __ldg(bhh + u * GN + 1024 + j);
        }
    }

    #pragma unroll
    for (int mt = 0; mt < 2; ++mt) {
        const int r0 = m0 + wm * 32 + mt * 16 + gr;
        #pragma unroll
        for (int rh = 0; rh < 2; ++rh) {
            const int row = r0 + rh * 8;
            const float* __restrict__ hp = Hi + ((size_t)row * UU + u) * HH;
            float* __restrict__ op = out + ((size_t)row * UU + u) * HH;
            #pragma unroll
            for (int nb = 0; nb < 2; ++nb) {
                const int jc = j0 + nb * 8 + 2 * d;
                const float2 h2 = *reinterpret_cast<const float2*>(hp + jc);
                float2 o2;
                #pragma unroll
                for (int c = 0; c < 2; ++c) {
                    const int q = rh * 2 + c;
                    const float rr = 1.0f / (1.0f + __expf(-(acc_rz[mt][nb][q]     + brs[nb][c])));
                    const float zz = 1.0f / (1.0f + __expf(-(acc_rz[mt][nb + 2][q] + bzs[nb][c])));
                    const float nn = tanhf(acc_xn[mt][nb][q] + bni[nb][c] +
                                           rr * (acc_hn[mt][nb][q] + bnh[nb][c]));
                    const float hv = c ? h2.y : h2.x;
                    const float ov = (1.0f - zz) * nn + zz * hv;
                    if (c) o2.y = ov; else o2.x = ov;
                }
                *reinterpret_cast<float2*>(op + jc) = o2;
            }
        }
    }
}

// ---------------------------------------------------------------------------
extern "C" void kernel_launch(void* const* d_in, const int* in_sizes, int n_in,
                              void* d_out, int out_size)
{
    const float* inputs = (const float*)d_in[0];  // [B,U,I]
    const float* hidden = (const float*)d_in[1];  // [B,U,H]
    const float* W_ih   = (const float*)d_in[2];  // [U,3H,I]
    const float* W_hh   = (const float*)d_in[3];  // [U,3H,H]
    const float* b_ih   = (const float*)d_in[4];  // [U,3H]
    const float* b_hh   = (const float*)d_in[5];  // [U,3H]
    float* out = (float*)d_out;                   // [B,U,H]

    cudaFuncSetAttribute(gru_fused_kernel,
                         cudaFuncAttributeMaxDynamicSharedMemorySize, SMEM_BYTES);

    cvt_all_kernel<<<(TOT4 + 255) / 256, 256>>>(
        (const float4*)inputs, (const float4*)hidden,
        (const float4*)W_ih,   (const float4*)W_hh);

    dim3 grid(HH / TOUT, BB / TM, UU);            // (16, 8, 8) = 1024 CTAs
    gru_fused_kernel<<<grid, 256, SMEM_BYTES>>>(hidden, b_ih, b_hh, out);
}